// round 12
// baseline (speedup 1.0000x reference)
#include <cuda_runtime.h>
#include <cstdint>

// Problem constants
#define A_CLS 50
#define C_CL  1024
#define F_LIT 1180
#define B_SMP 512
#define AC    (A_CLS * C_CL)     // 51200 clauses
#define NWORD 40                 // 10 float4-iterations x 4 ballot-words
#define CAP   8192               // candidate list capacity (expected ~0 used)

// Scratch (static __device__ globals — no runtime allocation)
// Bit order: iteration i covers literals [i*128, i*128+128); lane l's float4
// holds literals i*128+l*4 .. +3; ballot word (4i+j) packs component j across
// lanes. The SAME permutation is used for x and ta masks -> logic is exact.
__device__ uint4    d_maskPos[10][AC];    // full masks (rare-path verify only)
__device__ uint4    d_maskNeg[10][AC];
__device__ uint4    d_xbits[B_SMP][10];   // full x masks (rare-path verify)
__device__ unsigned d_x0[B_SMP];          // dense word-0 x (fast screen)
__device__ unsigned d_cand[CAP];          // candidate (ac*512 + sample)
__device__ unsigned d_cnt;                // candidate count
__device__ unsigned d_done;               // completion ticket

// ---------------------------------------------------------------------------
// pack_x: one warp per sample row (512 warps). Builds full x masks + dense
// word-0 array; resets candidate counter and ticket for this launch/replay.
// ---------------------------------------------------------------------------
__global__ void pack_x_kernel(const float* __restrict__ x) {
    int gtid = blockIdx.x * blockDim.x + threadIdx.x;
    int warp = gtid >> 5;
    int lane = threadIdx.x & 31;
    if (warp < B_SMP) {
        const float4* row4 = reinterpret_cast<const float4*>(x + (size_t)warp * F_LIT);
        #pragma unroll
        for (int i = 0; i < 10; i++) {
            float4 v = make_float4(0.f, 0.f, 0.f, 0.f);
            if (i * 128 + lane * 4 < F_LIT) v = __ldg(&row4[i * 32 + lane]);
            unsigned b0 = __ballot_sync(0xFFFFFFFFu, v.x > 0.5f);
            unsigned b1 = __ballot_sync(0xFFFFFFFFu, v.y > 0.5f);
            unsigned b2 = __ballot_sync(0xFFFFFFFFu, v.z > 0.5f);
            unsigned b3 = __ballot_sync(0xFFFFFFFFu, v.w > 0.5f);
            if (lane == 0) {
                d_xbits[warp][i] = make_uint4(b0, b1, b2, b3);
                if (i == 0) d_x0[warp] = b0;
            }
        }
    }
    if (gtid == 0) { d_cnt = 0u; d_done = 0u; }
}

// ---------------------------------------------------------------------------
// Fused pack + screen + (last block) output.
// Warp PAIR per clause, split by ROW-HALF (not polarity): even warp packs
// iterations 0..4 of BOTH pos and neg rows (10 independent LDG.128 — same
// MLP as the roofline pack), odd warp packs iterations 5..9. The even warp
// therefore holds word-0 of both polarities in registers and screens all 512
// samples in-warp (~45 extra instr, no syncs) — hidden under the 483 MB
// DRAM-bound read. Candidates (P ~ 2^-32/eval) go to a global list.
// A ticket lets the LAST block verify candidates (full 40 words) and write
// the clipped output directly — no eval kernel, no finish kernel.
// ---------------------------------------------------------------------------
__global__ __launch_bounds__(256, 6)
void pack_eval_kernel(const float* __restrict__ ta,
                      const float* __restrict__ clause_sign,
                      const int*   __restrict__ tptr,
                      float*       __restrict__ out) {
    __shared__ bool sLast;

    int warp = blockIdx.x * (blockDim.x >> 5) + (threadIdx.x >> 5);
    int lane = threadIdx.x & 31;
    int ac   = warp >> 1;       // grid sized so warp < AC*2 exactly
    int half = warp & 1;        // 0: iterations 0..4, 1: iterations 5..9

    const float4* pos4 = reinterpret_cast<const float4*>(ta) + (size_t)ac * 2 * (F_LIT / 4);
    const float4* neg4 = pos4 + (F_LIT / 4);

    unsigned p0 = 0, n0 = 0;
    #pragma unroll
    for (int ii = 0; ii < 5; ii++) {
        int i = half * 5 + ii;
        float4 vp = make_float4(0.f, 0.f, 0.f, 0.f);
        float4 vn = make_float4(0.f, 0.f, 0.f, 0.f);
        if (i * 128 + lane * 4 < F_LIT) {
            vp = __ldg(&pos4[i * 32 + lane]);
            vn = __ldg(&neg4[i * 32 + lane]);
        }
        unsigned bp0 = __ballot_sync(0xFFFFFFFFu, vp.x > 16.0f);
        unsigned bp1 = __ballot_sync(0xFFFFFFFFu, vp.y > 16.0f);
        unsigned bp2 = __ballot_sync(0xFFFFFFFFu, vp.z > 16.0f);
        unsigned bp3 = __ballot_sync(0xFFFFFFFFu, vp.w > 16.0f);
        unsigned bn0 = __ballot_sync(0xFFFFFFFFu, vn.x > 16.0f);
        unsigned bn1 = __ballot_sync(0xFFFFFFFFu, vn.y > 16.0f);
        unsigned bn2 = __ballot_sync(0xFFFFFFFFu, vn.z > 16.0f);
        unsigned bn3 = __ballot_sync(0xFFFFFFFFu, vn.w > 16.0f);
        if (lane == 0) {
            d_maskPos[i][ac] = make_uint4(bp0, bp1, bp2, bp3);
            d_maskNeg[i][ac] = make_uint4(bn0, bn1, bn2, bn3);
        }
        if (ii == 0) { p0 = bp0; n0 = bn0; }   // word 0 lives in half-0 warps
    }

    // ---- word-0 screen over all 512 samples (even warps only) ----
    if (half == 0) {
        const uint4* x0v = reinterpret_cast<const uint4*>(d_x0);
        #pragma unroll
        for (int r = 0; r < 4; r++) {
            uint4 x = __ldg(&x0v[r * 32 + lane]);          // samples 4e..4e+3
            unsigned v0 = (p0 & ~x.x) | (n0 & x.x);
            unsigned v1 = (p0 & ~x.y) | (n0 & x.y);
            unsigned v2 = (p0 & ~x.z) | (n0 & x.z);
            unsigned v3 = (p0 & ~x.w) | (n0 & x.w);
            if (min(min(v0, v1), min(v2, v3)) == 0u) {     // rare
                unsigned vv[4] = {v0, v1, v2, v3};
                int s0 = (r * 32 + lane) * 4;
                #pragma unroll 1
                for (int j = 0; j < 4; j++) {
                    if (vv[j] != 0u) continue;
                    unsigned idx = atomicAdd(&d_cnt, 1u);
                    if (idx < CAP)
                        d_cand[idx] = (unsigned)ac * 512u + (unsigned)(s0 + j);
                }
            }
        }
    }

    // ---- completion ticket; last block resolves candidates + writes out ----
    __syncthreads();
    if (threadIdx.x == 0) {
        __threadfence();                          // release masks + candidates
        unsigned t = atomicAdd(&d_done, 1u);
        sLast = (t == gridDim.x - 1);
    }
    __syncthreads();
    if (sLast) {
        __threadfence();                          // acquire
        // T dtype is ambiguous (python int in the reference): small
        // non-negative bit-patterns -> int32, anything else -> float32 bits.
        int ti = *tptr;
        float T = (ti >= 0 && ti < (1 << 23)) ? (float)ti : __int_as_float(ti);
        unsigned cnt = d_cnt; if (cnt > CAP) cnt = CAP;
        for (int i = threadIdx.x; i < B_SMP * A_CLS; i += blockDim.x) {
            int b = i / A_CLS, a = i % A_CLS;
            float v = 0.0f;
            for (unsigned k = 0; k < cnt; k++) {  // typically cnt == 0
                unsigned e   = d_cand[k];
                unsigned cac = e >> 9;
                int      cs  = (int)(e & 511u);
                if (cs != b || (int)(cac >> 10) != a) continue;
                const unsigned* xr = reinterpret_cast<const unsigned*>(&d_xbits[cs][0]);
                bool fire = true;
                for (int w = 0; w < NWORD && fire; w++) {
                    unsigned xx = xr[w];
                    unsigned pw = reinterpret_cast<const unsigned*>(&d_maskPos[w >> 2][cac])[w & 3];
                    unsigned nw = reinterpret_cast<const unsigned*>(&d_maskNeg[w >> 2][cac])[w & 3];
                    if ((pw & ~xx) | (nw & xx)) fire = false;
                }
                if (fire) v += __ldg(&clause_sign[cac]);
            }
            out[i] = fminf(fmaxf(v, -T), T);
        }
    }
}

// ---------------------------------------------------------------------------
extern "C" void kernel_launch(void* const* d_in, const int* in_sizes, int n_in,
                              void* d_out, int out_size) {
    const float* x  = (const float*)d_in[0];  // binary_features [512, 1180]
    const float* ta = (const float*)d_in[1];  // ta_state [50, 1024, 2, 1180]
    const float* cs = (const float*)d_in[2];  // clause_sign [50, 1024]
    const int*   Tp = (const int*)  d_in[3];  // T scalar

    (void)in_sizes; (void)n_in; (void)out_size;

    // 1. pack x masks + reset counters: 512 warps
    pack_x_kernel<<<64, 256>>>(x);
    // 2. fused ta-pack + screen + output: warp-pair per clause, 8 warps/block
    pack_eval_kernel<<<AC * 2 / 8, 256>>>(ta, cs, Tp, (float*)d_out);
}

// round 13
// speedup vs baseline: 2.3935x; 2.3935x over previous
#include <cuda_runtime.h>
#include <cstdint>

// Problem constants
#define A_CLS 50
#define C_CL  1024
#define F_LIT 1180
#define B_SMP 512
#define AC    (A_CLS * C_CL)     // 51200 clauses
#define NW    37                 // ceil(1180/32) x-mask words (plain layout)

// Scratch (static __device__ globals — no runtime allocation)
// Plain bit layout: x word w, bit l = x[32w + l].
__device__ unsigned d_xbits[B_SMP][NW];   // full x masks (verify path)
__device__ unsigned d_x0[B_SMP];          // word 0 (fast screen)
__device__ float    d_votes[B_SMP * A_CLS];
__device__ unsigned d_done;               // completion ticket

// ---------------------------------------------------------------------------
// pack_x: one warp per sample row (512 warps, 2.4 MB). Builds x masks +
// dense word-0 array; zeroes votes and the ticket for this launch/replay.
// ---------------------------------------------------------------------------
__global__ void pack_x_kernel(const float* __restrict__ x) {
    int gtid = blockIdx.x * blockDim.x + threadIdx.x;
    int warp = gtid >> 5;
    int lane = threadIdx.x & 31;
    if (warp < B_SMP) {
        const float* row = x + (size_t)warp * F_LIT;
        #pragma unroll
        for (int w = 0; w < NW; w++) {
            int f = w * 32 + lane;
            bool on = (f < F_LIT) && (row[f] > 0.5f);
            unsigned bits = __ballot_sync(0xFFFFFFFFu, on);
            if (lane == 0) {
                d_xbits[warp][w] = bits;
                if (w == 0) d_x0[warp] = bits;
            }
        }
    }
    for (int i = gtid; i < B_SMP * A_CLS; i += gridDim.x * blockDim.x)
        d_votes[i] = 0.0f;
    if (gtid == 0) d_done = 0u;
}

// ---------------------------------------------------------------------------
// Screen + verify + (last block) output. One warp per clause.
//
// KEY INSIGHT: a clause fires iff ALL literals are clean, so screening on
// just the FIRST 32 literals (1e-8 pass rate on this data) means we read
// 2 x 128 B per clause (13 MB total) instead of the full 483 MB ta_state.
// Candidates are verified EXACTLY against the raw ta row (9.4 KB, rare:
// ~0.26 expected across all 26.2M pairs), so no packed clause masks exist.
// Votes go to global via atomicAdd (~never); a ticket lets the last block
// clip and write the output. Exact algorithm, ~37x less DRAM traffic.
// ---------------------------------------------------------------------------
__global__ __launch_bounds__(256, 6)
void screen_kernel(const float* __restrict__ ta,
                   const float* __restrict__ clause_sign,
                   const int*   __restrict__ tptr,
                   float*       __restrict__ out) {
    __shared__ __align__(16) unsigned sx0[B_SMP];
    __shared__ bool sLast;

    // all 512 word-0 x masks (2 KB), cooperative coalesced load
    for (int i = threadIdx.x; i < B_SMP / 4; i += blockDim.x)
        reinterpret_cast<uint4*>(sx0)[i] = reinterpret_cast<const uint4*>(d_x0)[i];
    __syncthreads();

    int ac   = blockIdx.x * (blockDim.x >> 5) + (threadIdx.x >> 5); // grid-sized exactly
    int lane = threadIdx.x & 31;
    int a    = ac >> 10;                       // C_CL == 1024

    const float* pos = ta + (size_t)ac * 2 * F_LIT;
    const float* neg = pos + F_LIT;

    // masks of the first 32 literals — the only ta bytes the fast path reads
    unsigned p0 = __ballot_sync(0xFFFFFFFFu, __ldg(pos + lane) > 16.0f);
    unsigned n0 = __ballot_sync(0xFFFFFFFFu, __ldg(neg + lane) > 16.0f);

    // screen all 512 samples: lane handles samples 4*(r*32+lane) .. +3
    #pragma unroll
    for (int r = 0; r < 4; r++) {
        uint4 x = *reinterpret_cast<const uint4*>(&sx0[(r * 32 + lane) * 4]);
        unsigned v0 = (p0 & ~x.x) | (n0 & x.x);
        unsigned v1 = (p0 & ~x.y) | (n0 & x.y);
        unsigned v2 = (p0 & ~x.z) | (n0 & x.z);
        unsigned v3 = (p0 & ~x.w) | (n0 & x.w);
        if (min(min(v0, v1), min(v2, v3)) == 0u) {      // ~1e-8 per sample
            unsigned vv[4] = {v0, v1, v2, v3};
            int s0 = (r * 32 + lane) * 4;
            #pragma unroll 1
            for (int j = 0; j < 4; j++) {
                if (vv[j] != 0u) continue;
                int b = s0 + j;
                // exact verify: all 1180 literals against the raw ta row
                bool fire = true;
                #pragma unroll 1
                for (int w = 0; w < NW && fire; w++) {
                    unsigned xw = d_xbits[b][w];
                    int base = w * 32;
                    int lim  = (F_LIT - base < 32) ? (F_LIT - base) : 32;
                    #pragma unroll 1
                    for (int l = 0; l < lim; l++) {
                        bool xb = (xw >> l) & 1u;
                        float pv = __ldg(pos + base + l);
                        float nv = __ldg(neg + base + l);
                        if ((pv > 16.0f && !xb) || (nv > 16.0f && xb)) {
                            fire = false; break;
                        }
                    }
                }
                if (fire)
                    atomicAdd(&d_votes[b * A_CLS + a], __ldg(&clause_sign[ac]));
            }
        }
    }

    // completion ticket; last block clips votes and writes the output
    __syncthreads();
    if (threadIdx.x == 0) {
        __threadfence();                         // release votes
        unsigned t = atomicAdd(&d_done, 1u);
        sLast = (t == gridDim.x - 1);
    }
    __syncthreads();
    if (sLast) {
        __threadfence();                         // acquire votes
        // T dtype is ambiguous (python int in the reference): small
        // non-negative bit-patterns -> int32, anything else -> float32 bits.
        int ti = *tptr;
        float T = (ti >= 0 && ti < (1 << 23)) ? (float)ti : __int_as_float(ti);
        for (int i = threadIdx.x; i < B_SMP * A_CLS; i += blockDim.x) {
            float v = d_votes[i];                // layout [B, A] == out
            out[i] = fminf(fmaxf(v, -T), T);
        }
    }
}

// ---------------------------------------------------------------------------
extern "C" void kernel_launch(void* const* d_in, const int* in_sizes, int n_in,
                              void* d_out, int out_size) {
    const float* x  = (const float*)d_in[0];  // binary_features [512, 1180]
    const float* ta = (const float*)d_in[1];  // ta_state [50, 1024, 2, 1180]
    const float* cs = (const float*)d_in[2];  // clause_sign [50, 1024]
    const int*   Tp = (const int*)  d_in[3];  // T scalar

    (void)in_sizes; (void)n_in; (void)out_size;

    // 1. pack x masks + zero votes/ticket: 512 warps, 2.4 MB
    pack_x_kernel<<<64, 256>>>(x);
    // 2. screen (13 MB of ta) + exact verify + output: warp per clause
    screen_kernel<<<AC / 8, 256>>>(ta, cs, Tp, (float*)d_out);
}

// round 14
// speedup vs baseline: 2.5411x; 1.0616x over previous
#include <cuda_runtime.h>
#include <cstdint>

// Problem constants
#define A_CLS 50
#define C_CL  1024
#define F_LIT 1180
#define B_SMP 512
#define AC    (A_CLS * C_CL)     // 51200 clauses
#define NW    37                 // ceil(1180/32) x-mask words (plain layout)

// Scratch (static __device__ globals — no runtime allocation)
// Plain bit layout: x word w, bit l = x[32w + l].
__device__ unsigned d_xbits[B_SMP][NW];   // full x masks (verify path)
__device__ unsigned d_x0[B_SMP];          // word 0 (fast screen)
__device__ float    d_votes[B_SMP * A_CLS];
__device__ unsigned d_done;               // completion ticket

// ---------------------------------------------------------------------------
// pack_x: one warp per sample row (512 warps, 2.4 MB). Builds x masks +
// dense word-0 array; zeroes votes and the ticket for this launch/replay.
// ---------------------------------------------------------------------------
__global__ void pack_x_kernel(const float* __restrict__ x) {
    int gtid = blockIdx.x * blockDim.x + threadIdx.x;
    int warp = gtid >> 5;
    int lane = threadIdx.x & 31;
    if (warp < B_SMP) {
        const float* row = x + (size_t)warp * F_LIT;
        #pragma unroll
        for (int w = 0; w < NW; w++) {
            int f = w * 32 + lane;
            bool on = (f < F_LIT) && (row[f] > 0.5f);
            unsigned bits = __ballot_sync(0xFFFFFFFFu, on);
            if (lane == 0) {
                d_xbits[warp][w] = bits;
                if (w == 0) d_x0[warp] = bits;
            }
        }
    }
    for (int i = gtid; i < B_SMP * A_CLS; i += gridDim.x * blockDim.x)
        d_votes[i] = 0.0f;
    if (gtid == 0) d_done = 0u;
}

// ---------------------------------------------------------------------------
// Screen + verify + (last block) output. One warp per clause.
//
// KEY INSIGHT: a clause fires iff ALL literals are clean, so screening on
// just the FIRST 32 literals (1e-8 pass rate on this data) means we read
// 2 x 128 B per clause (13 MB total) instead of the full 483 MB ta_state.
// Candidates are verified EXACTLY against the raw ta row (9.4 KB, rare:
// ~0.26 expected across all 26.2M pairs), so no packed clause masks exist.
// Votes go to global via atomicAdd (~never); a ticket lets the last block
// clip and write the output. Exact algorithm, ~37x less DRAM traffic.
// ---------------------------------------------------------------------------
__global__ __launch_bounds__(256, 6)
void screen_kernel(const float* __restrict__ ta,
                   const float* __restrict__ clause_sign,
                   const int*   __restrict__ tptr,
                   float*       __restrict__ out) {
    __shared__ __align__(16) unsigned sx0[B_SMP];
    __shared__ bool sLast;

    // all 512 word-0 x masks (2 KB), cooperative coalesced load
    for (int i = threadIdx.x; i < B_SMP / 4; i += blockDim.x)
        reinterpret_cast<uint4*>(sx0)[i] = reinterpret_cast<const uint4*>(d_x0)[i];
    __syncthreads();

    int ac   = blockIdx.x * (blockDim.x >> 5) + (threadIdx.x >> 5); // grid-sized exactly
    int lane = threadIdx.x & 31;
    int a    = ac >> 10;                       // C_CL == 1024

    const float* pos = ta + (size_t)ac * 2 * F_LIT;
    const float* neg = pos + F_LIT;

    // masks of the first 32 literals — the only ta bytes the fast path reads
    unsigned p0 = __ballot_sync(0xFFFFFFFFu, __ldg(pos + lane) > 16.0f);
    unsigned n0 = __ballot_sync(0xFFFFFFFFu, __ldg(neg + lane) > 16.0f);

    // screen all 512 samples: lane handles samples 4*(r*32+lane) .. +3
    #pragma unroll
    for (int r = 0; r < 4; r++) {
        uint4 x = *reinterpret_cast<const uint4*>(&sx0[(r * 32 + lane) * 4]);
        unsigned v0 = (p0 & ~x.x) | (n0 & x.x);
        unsigned v1 = (p0 & ~x.y) | (n0 & x.y);
        unsigned v2 = (p0 & ~x.z) | (n0 & x.z);
        unsigned v3 = (p0 & ~x.w) | (n0 & x.w);
        if (min(min(v0, v1), min(v2, v3)) == 0u) {      // ~1e-8 per sample
            unsigned vv[4] = {v0, v1, v2, v3};
            int s0 = (r * 32 + lane) * 4;
            #pragma unroll 1
            for (int j = 0; j < 4; j++) {
                if (vv[j] != 0u) continue;
                int b = s0 + j;
                // exact verify: all 1180 literals against the raw ta row
                bool fire = true;
                #pragma unroll 1
                for (int w = 0; w < NW && fire; w++) {
                    unsigned xw = d_xbits[b][w];
                    int base = w * 32;
                    int lim  = (F_LIT - base < 32) ? (F_LIT - base) : 32;
                    #pragma unroll 1
                    for (int l = 0; l < lim; l++) {
                        bool xb = (xw >> l) & 1u;
                        float pv = __ldg(pos + base + l);
                        float nv = __ldg(neg + base + l);
                        if ((pv > 16.0f && !xb) || (nv > 16.0f && xb)) {
                            fire = false; break;
                        }
                    }
                }
                if (fire)
                    atomicAdd(&d_votes[b * A_CLS + a], __ldg(&clause_sign[ac]));
            }
        }
    }

    // completion ticket; last block clips votes and writes the output
    __syncthreads();
    if (threadIdx.x == 0) {
        __threadfence();                         // release votes
        unsigned t = atomicAdd(&d_done, 1u);
        sLast = (t == gridDim.x - 1);
    }
    __syncthreads();
    if (sLast) {
        __threadfence();                         // acquire votes
        // T dtype is ambiguous (python int in the reference): small
        // non-negative bit-patterns -> int32, anything else -> float32 bits.
        int ti = *tptr;
        float T = (ti >= 0 && ti < (1 << 23)) ? (float)ti : __int_as_float(ti);
        for (int i = threadIdx.x; i < B_SMP * A_CLS; i += blockDim.x) {
            float v = d_votes[i];                // layout [B, A] == out
            out[i] = fminf(fmaxf(v, -T), T);
        }
    }
}

// ---------------------------------------------------------------------------
extern "C" void kernel_launch(void* const* d_in, const int* in_sizes, int n_in,
                              void* d_out, int out_size) {
    const float* x  = (const float*)d_in[0];  // binary_features [512, 1180]
    const float* ta = (const float*)d_in[1];  // ta_state [50, 1024, 2, 1180]
    const float* cs = (const float*)d_in[2];  // clause_sign [50, 1024]
    const int*   Tp = (const int*)  d_in[3];  // T scalar

    (void)in_sizes; (void)n_in; (void)out_size;

    // 1. pack x masks + zero votes/ticket: 512 warps, 2.4 MB
    pack_x_kernel<<<64, 256>>>(x);
    // 2. screen (13 MB of ta) + exact verify + output: warp per clause
    screen_kernel<<<AC / 8, 256>>>(ta, cs, Tp, (float*)d_out);
}

// round 15
// speedup vs baseline: 2.5433x; 1.0009x over previous
#include <cuda_runtime.h>
#include <cstdint>

// Problem constants
#define A_CLS 50
#define C_CL  1024
#define F_LIT 1180
#define B_SMP 512
#define AC    (A_CLS * C_CL)     // 51200 clauses
#define NW    37                 // ceil(1180/32) x-mask words (plain layout)

// Scratch (static __device__ globals — no runtime allocation)
// Plain bit layout: x word w, bit l = x[32w + l].
__device__ unsigned d_xbits[B_SMP][NW];   // full x masks (verify path)
__device__ unsigned d_x0[B_SMP];          // word 0 (fast screen)
__device__ float    d_votes[B_SMP * A_CLS];
__device__ unsigned d_done;               // completion ticket

// ---------------------------------------------------------------------------
// pack_x: one warp per sample row (512 warps, 2.4 MB). Builds x masks +
// dense word-0 array; zeroes votes and the ticket for this launch/replay.
// ---------------------------------------------------------------------------
__global__ void pack_x_kernel(const float* __restrict__ x) {
    int gtid = blockIdx.x * blockDim.x + threadIdx.x;
    int warp = gtid >> 5;
    int lane = threadIdx.x & 31;
    if (warp < B_SMP) {
        const float* row = x + (size_t)warp * F_LIT;
        #pragma unroll
        for (int w = 0; w < NW; w++) {
            int f = w * 32 + lane;
            bool on = (f < F_LIT) && (row[f] > 0.5f);
            unsigned bits = __ballot_sync(0xFFFFFFFFu, on);
            if (lane == 0) {
                d_xbits[warp][w] = bits;
                if (w == 0) d_x0[warp] = bits;
            }
        }
    }
    for (int i = gtid; i < B_SMP * A_CLS; i += gridDim.x * blockDim.x)
        d_votes[i] = 0.0f;
    if (gtid == 0) d_done = 0u;
}

// ---------------------------------------------------------------------------
// Screen + verify + (last block) output. One warp per FOUR clauses.
//
// Screening on the first 32 literals (P(clean) = 2^-32 per eval) needs only
// 2 x 128 B per clause (13 MB total) instead of the 483 MB ta_state read.
// R14 ran this 1 clause/warp and was latency-bound (issue 37%, DRAM 5%):
// MLP=2 and 6400 tiny blocks. Now each warp screens 4 consecutive clauses —
// all 8 row loads issued up front (MLP=8), 8 ballots, then one fused screen
// whose 64 evals/x-word-iteration collapse into a single `grand` min and ONE
// branch per warp. Grid 1600 blocks. Candidates (~0.006 expected per launch)
// recompute + verify exactly against the raw ta rows. Votes via atomicAdd
// (~never); ticket lets the last block clip and write the output.
// ---------------------------------------------------------------------------
__global__ __launch_bounds__(256, 6)
void screen_kernel(const float* __restrict__ ta,
                   const float* __restrict__ clause_sign,
                   const int*   __restrict__ tptr,
                   float*       __restrict__ out) {
    __shared__ __align__(16) unsigned sx0[B_SMP];
    __shared__ bool sLast;

    // all 512 word-0 x masks (2 KB), cooperative coalesced load
    for (int i = threadIdx.x; i < B_SMP / 4; i += blockDim.x)
        reinterpret_cast<uint4*>(sx0)[i] = reinterpret_cast<const uint4*>(d_x0)[i];
    __syncthreads();

    int wid  = blockIdx.x * (blockDim.x >> 5) + (threadIdx.x >> 5);
    int lane = threadIdx.x & 31;
    int ac0  = wid * 4;                       // 12800 warps x 4 clauses = AC

    // 8 independent 128B row loads (first 32 literals of pos/neg, 4 clauses)
    float pv[4], nv[4];
    #pragma unroll
    for (int k = 0; k < 4; k++) {
        const float* pos = ta + (size_t)(ac0 + k) * 2 * F_LIT;
        pv[k] = __ldg(pos + lane);
        nv[k] = __ldg(pos + F_LIT + lane);
    }
    unsigned p0[4], n0[4];
    #pragma unroll
    for (int k = 0; k < 4; k++) {
        p0[k] = __ballot_sync(0xFFFFFFFFu, pv[k] > 16.0f);
        n0[k] = __ballot_sync(0xFFFFFFFFu, nv[k] > 16.0f);
    }

    // fused screen: 4 x-word iterations x 16 LOP3, one grand min, one branch
    unsigned grand = 0xFFFFFFFFu;
    #pragma unroll
    for (int r = 0; r < 4; r++) {
        uint4 x = *reinterpret_cast<const uint4*>(&sx0[(r * 32 + lane) * 4]);
        #pragma unroll
        for (int k = 0; k < 4; k++) {
            unsigned v0 = (p0[k] & ~x.x) | (n0[k] & x.x);   // 1 LOP3 each
            unsigned v1 = (p0[k] & ~x.y) | (n0[k] & x.y);
            unsigned v2 = (p0[k] & ~x.z) | (n0[k] & x.z);
            unsigned v3 = (p0[k] & ~x.w) | (n0[k] & x.w);
            grand = min(grand, min(min(v0, v1), min(v2, v3)));
        }
    }

    // cold path: recompute per-eval results, verify exactly vs raw ta
    if (grand == 0u) {                        // P ~ 2e-10 per lane
        #pragma unroll 1
        for (int r = 0; r < 4; r++) {
            uint4 x = *reinterpret_cast<const uint4*>(&sx0[(r * 32 + lane) * 4]);
            unsigned xs[4] = {x.x, x.y, x.z, x.w};
            #pragma unroll 1
            for (int k = 0; k < 4; k++) {
                int ac = ac0 + k;
                const float* pos = ta + (size_t)ac * 2 * F_LIT;
                const float* neg = pos + F_LIT;
                #pragma unroll 1
                for (int j = 0; j < 4; j++) {
                    if (((p0[k] & ~xs[j]) | (n0[k] & xs[j])) != 0u) continue;
                    int b = (r * 32 + lane) * 4 + j;
                    bool fire = true;
                    #pragma unroll 1
                    for (int w = 0; w < NW && fire; w++) {
                        unsigned xw = d_xbits[b][w];
                        int base = w * 32;
                        int lim  = (F_LIT - base < 32) ? (F_LIT - base) : 32;
                        #pragma unroll 1
                        for (int l = 0; l < lim; l++) {
                            bool xb = (xw >> l) & 1u;
                            if ((__ldg(pos + base + l) > 16.0f && !xb) ||
                                (__ldg(neg + base + l) > 16.0f &&  xb)) {
                                fire = false; break;
                            }
                        }
                    }
                    if (fire)
                        atomicAdd(&d_votes[b * A_CLS + (ac >> 10)],
                                  __ldg(&clause_sign[ac]));
                }
            }
        }
    }

    // completion ticket; last block clips votes and writes the output
    __syncthreads();
    if (threadIdx.x == 0) {
        __threadfence();                         // release votes
        unsigned t = atomicAdd(&d_done, 1u);
        sLast = (t == gridDim.x - 1);
    }
    __syncthreads();
    if (sLast) {
        __threadfence();                         // acquire votes
        // T dtype is ambiguous (python int in the reference): small
        // non-negative bit-patterns -> int32, anything else -> float32 bits.
        int ti = *tptr;
        float T = (ti >= 0 && ti < (1 << 23)) ? (float)ti : __int_as_float(ti);
        for (int i = threadIdx.x; i < B_SMP * A_CLS; i += blockDim.x) {
            float v = d_votes[i];                // layout [B, A] == out
            out[i] = fminf(fmaxf(v, -T), T);
        }
    }
}

// ---------------------------------------------------------------------------
extern "C" void kernel_launch(void* const* d_in, const int* in_sizes, int n_in,
                              void* d_out, int out_size) {
    const float* x  = (const float*)d_in[0];  // binary_features [512, 1180]
    const float* ta = (const float*)d_in[1];  // ta_state [50, 1024, 2, 1180]
    const float* cs = (const float*)d_in[2];  // clause_sign [50, 1024]
    const int*   Tp = (const int*)  d_in[3];  // T scalar

    (void)in_sizes; (void)n_in; (void)out_size;

    // 1. pack x masks + zero votes/ticket: 512 warps, 2.4 MB
    pack_x_kernel<<<64, 256>>>(x);
    // 2. screen (13 MB of ta, 4 clauses/warp) + exact verify + output
    screen_kernel<<<AC / 4 / 8, 256>>>(ta, cs, Tp, (float*)d_out);
}